// round 15
// baseline (speedup 1.0000x reference)
#include <cuda_runtime.h>

typedef unsigned long long ULL;

static constexpr int Bt = 1024;
static constexpr int Tt = 512;
static constexpr int Ft = 128;   // input features
static constexpr int Ht = 64;    // hidden
static constexpr int Gt = 192;   // 3*H gates
static constexpr int At = 18;    // actions
static constexpr int BM = 8;     // batch rows per CTA in recurrence kernel

// Scratch for precomputed input projection of layer 0: [t][b][192], 384 MB.
__device__ float g_gx0[(size_t)Tt * Bt * Gt];

// ---------------------------------------------------------------------------
// helpers
// ---------------------------------------------------------------------------
__device__ __forceinline__ void ffma2(ULL& d, ULL a, ULL b) {
    // packed fp32x2 fused multiply-add (Blackwell); exact fp32 per-lane math
    asm("fma.rn.f32x2 %0, %1, %2, %0;" : "+l"(d) : "l"(a), "l"(b));
}
__device__ __forceinline__ ULL f2u(float lo, float hi) {
    return (ULL)__float_as_uint(lo) | ((ULL)__float_as_uint(hi) << 32);
}
__device__ __forceinline__ float ufold(ULL v) {
    return __uint_as_float((unsigned)v) + __uint_as_float((unsigned)(v >> 32));
}
__device__ __forceinline__ float sigf(float x) {
    return __fdividef(1.0f, 1.0f + __expf(-x));      // graceful at +-inf
}
__device__ __forceinline__ float tanhf_fast(float x) {
    return 1.0f - __fdividef(2.0f, __expf(2.0f * x) + 1.0f);
}

// ---------------------------------------------------------------------------
// Kernel 1: gx0[t][b][j] = b_ih_l0[j] + sum_k state[b][t][k] * W_ih_l0[j][k]
//   M = B*T = 524288 rows, N = 192, K = 128.  32 rows / CTA, 256 threads.
// ---------------------------------------------------------------------------
__global__ void __launch_bounds__(256, 1)
gx0_kernel(const float* __restrict__ state,
           const float* __restrict__ Wih0,
           const float* __restrict__ bih0) {
    extern __shared__ float4 sm1[];
    float4* Ws4 = sm1;                 // [k4 0..31][j 0..191]
    float4* xs4 = sm1 + 32 * 192;      // [k4 0..31][m], row stride 65 (pad)

    const int tid = threadIdx.x;
    const int r0 = blockIdx.x * 32;

    const float4* gW4 = reinterpret_cast<const float4*>(Wih0);
    for (int idx = tid; idx < 192 * 32; idx += 256) {
        int j = idx >> 5, k4 = idx & 31;
        Ws4[k4 * 192 + j] = gW4[idx];
    }
    const float4* gX4 = reinterpret_cast<const float4*>(state);
    for (int idx = tid; idx < 32 * 32; idx += 256) {
        int mm = idx >> 5, k4 = idx & 31;
        xs4[k4 * 65 + mm] = gX4[(r0 + mm) * 32 + k4];
    }
    __syncthreads();

    const int lane  = tid & 31;
    const int w     = tid >> 5;        // 8 warps partition the 192 j's
    const int m8    = lane & 7;
    const int jl    = lane >> 3;
    const int jbase = w * 24 + jl;     // j = jbase + 4*q, q = 0..5

    ULL acc[6][4];
    #pragma unroll
    for (int q = 0; q < 6; q++) {
        float bq = __ldg(&bih0[jbase + 4 * q]);
        #pragma unroll
        for (int mi = 0; mi < 4; mi++) acc[q][mi] = f2u(bq, 0.0f);
    }

    #pragma unroll 4
    for (int k4 = 0; k4 < 32; k4++) {
        ulonglong2 xv[4];
        #pragma unroll
        for (int mi = 0; mi < 4; mi++)
            xv[mi] = *reinterpret_cast<const ulonglong2*>(&xs4[k4 * 65 + m8 + 8 * mi]);
        #pragma unroll
        for (int q = 0; q < 6; q++) {
            ulonglong2 wv = *reinterpret_cast<const ulonglong2*>(&Ws4[k4 * 192 + jbase + 4 * q]);
            #pragma unroll
            for (int mi = 0; mi < 4; mi++) {
                ffma2(acc[q][mi], wv.x, xv[mi].x);
                ffma2(acc[q][mi], wv.y, xv[mi].y);
            }
        }
    }

    #pragma unroll
    for (int mi = 0; mi < 4; mi++) {
        int r = r0 + m8 + 8 * mi;      // row = b*T + t
        int b = r >> 9;
        int t = r & 511;
        float* op = g_gx0 + (size_t)t * (Bt * Gt) + (size_t)b * Gt;
        #pragma unroll
        for (int q = 0; q < 6; q++)
            op[jbase + 4 * q] = ufold(acc[q][mi]);
    }
}

// ---------------------------------------------------------------------------
// Kernel 2: persistent 2-layer GRU recurrence over T=512 steps + FC epilogue.
//   128 CTAs x 128 threads, 8 batch rows each.
// ---------------------------------------------------------------------------
__global__ void __launch_bounds__(128, 1)
gru_kernel(const float* __restrict__ Whh0, const float* __restrict__ bhh0,
           const float* __restrict__ Wih1, const float* __restrict__ bih1,
           const float* __restrict__ Whh1, const float* __restrict__ bhh1,
           const float* __restrict__ fc3w, const float* __restrict__ fc3b,
           float* __restrict__ out) {
    extern __shared__ float4 sm2[];
    float4* W0s  = sm2;                    // [k4 0..15][j 0..191]
    float4* W1is = sm2 + 16 * 192;
    float4* W1hs = sm2 + 2 * 16 * 192;
    float* fbase = reinterpret_cast<float*>(sm2 + 3 * 16 * 192);
    float* h0s  = fbase;                   // [8][68]  (pad-68: conflict-free)
    float* h1s  = fbase + 544;
    float* bufA = fbase + 1088;            // [8][200] gh0 / gx1
    float* bufB = fbase + 1088 + 1600;     // [8][200] gh1
    float* sb0  = fbase + 1088 + 3200;     // b_hh_l0  [192]
    float* sb1i = sb0 + 192;
    float* sb1h = sb1i + 192;
    float* sfw  = sb1h + 192;              // fc3_w [18][64]
    float* sfb  = sfw + 1152;              // fc3_b [18]

    const int tid = threadIdx.x;
    const int b0  = blockIdx.x * BM;

    // --- one-time loads (transpose weights into [k4][j] float4 layout) ---
    const float4* g0  = reinterpret_cast<const float4*>(Whh0);
    const float4* g1i = reinterpret_cast<const float4*>(Wih1);
    const float4* g1h = reinterpret_cast<const float4*>(Whh1);
    for (int idx = tid; idx < 192 * 16; idx += 128) {
        int j = idx >> 4, k4 = idx & 15;
        W0s [k4 * 192 + j] = g0 [idx];
        W1is[k4 * 192 + j] = g1i[idx];
        W1hs[k4 * 192 + j] = g1h[idx];
    }
    for (int idx = tid; idx < 192; idx += 128) {
        sb0[idx] = bhh0[idx]; sb1i[idx] = bih1[idx]; sb1h[idx] = bhh1[idx];
    }
    for (int idx = tid; idx < 1152; idx += 128) sfw[idx] = fc3w[idx];
    if (tid < At) sfb[tid] = fc3b[tid];
    for (int idx = tid; idx < 544; idx += 128) { h0s[idx] = 0.0f; h1s[idx] = 0.0f; }
    __syncthreads();

    const int lane  = tid & 31;
    const int w     = tid >> 5;           // 4 warps x 48 j's
    const int m     = lane & 7;           // batch row within tile
    const int jl    = lane >> 3;
    const int jbase = w * 48 + jl;        // j = jbase + 4*q, q = 0..11

    int gm[4], gk[4];
    #pragma unroll
    for (int i = 0; i < 4; i++) { int idx = tid + 128 * i; gm[i] = idx >> 6; gk[i] = idx & 63; }

    #pragma unroll 1
    for (int t = 0; t < Tt; t++) {
        // prefetch this step's gx0 tile (consumed in gate phase; DRAM latency
        // hides under the layer-0 matvec)
        const float* gp = g_gx0 + (size_t)t * (Bt * Gt) + (size_t)b0 * Gt;
        float gxr[4], gxz[4], gxn[4];
        #pragma unroll
        for (int i = 0; i < 4; i++) {
            const float* p = gp + gm[i] * Gt + gk[i];
            gxr[i] = __ldg(p); gxz[i] = __ldg(p + 64); gxn[i] = __ldg(p + 128);
        }

        // ---- layer 0 recurrent matvec: gh0 = b_hh_l0 + W_hh_l0 @ h0 ----
        {
            ULL acc[12];
            #pragma unroll
            for (int q = 0; q < 12; q++) acc[q] = f2u(sb0[jbase + 4 * q], 0.0f);
            #pragma unroll 4
            for (int k4 = 0; k4 < 16; k4++) {
                ulonglong2 hv = *reinterpret_cast<const ulonglong2*>(&h0s[m * 68 + k4 * 4]);
                #pragma unroll
                for (int q = 0; q < 12; q++) {
                    ulonglong2 wv = *reinterpret_cast<const ulonglong2*>(&W0s[k4 * 192 + jbase + 4 * q]);
                    ffma2(acc[q], wv.x, hv.x);
                    ffma2(acc[q], wv.y, hv.y);
                }
            }
            #pragma unroll
            for (int q = 0; q < 12; q++)
                bufA[m * 200 + jbase + 4 * q] = ufold(acc[q]);
        }
        __syncthreads();

        // ---- layer 0 gates ----
        #pragma unroll
        for (int i = 0; i < 4; i++) {
            const float* hb = &bufA[gm[i] * 200];
            float r = sigf(gxr[i] + hb[gk[i]]);
            float z = sigf(gxz[i] + hb[64 + gk[i]]);
            float n = tanhf_fast(gxn[i] + r * hb[128 + gk[i]]);
            float ho = h0s[gm[i] * 68 + gk[i]];
            h0s[gm[i] * 68 + gk[i]] = n + z * (ho - n);
        }
        __syncthreads();

        // ---- layer 1 matvecs: gx1 = b_ih_l1 + W_ih_l1 @ h0 ; gh1 = b_hh_l1 + W_hh_l1 @ h1 ----
        {
            ULL ax[12], ah[12];
            #pragma unroll
            for (int q = 0; q < 12; q++) {
                ax[q] = f2u(sb1i[jbase + 4 * q], 0.0f);
                ah[q] = f2u(sb1h[jbase + 4 * q], 0.0f);
            }
            #pragma unroll 2
            for (int k4 = 0; k4 < 16; k4++) {
                ulonglong2 h0v = *reinterpret_cast<const ulonglong2*>(&h0s[m * 68 + k4 * 4]);
                ulonglong2 h1v = *reinterpret_cast<const ulonglong2*>(&h1s[m * 68 + k4 * 4]);
                #pragma unroll
                for (int q = 0; q < 12; q++) {
                    ulonglong2 wx = *reinterpret_cast<const ulonglong2*>(&W1is[k4 * 192 + jbase + 4 * q]);
                    ulonglong2 wh = *reinterpret_cast<const ulonglong2*>(&W1hs[k4 * 192 + jbase + 4 * q]);
                    ffma2(ax[q], wx.x, h0v.x);
                    ffma2(ax[q], wx.y, h0v.y);
                    ffma2(ah[q], wh.x, h1v.x);
                    ffma2(ah[q], wh.y, h1v.y);
                }
            }
            #pragma unroll
            for (int q = 0; q < 12; q++) {
                bufA[m * 200 + jbase + 4 * q] = ufold(ax[q]);
                bufB[m * 200 + jbase + 4 * q] = ufold(ah[q]);
            }
        }
        __syncthreads();

        // ---- layer 1 gates ----
        #pragma unroll
        for (int i = 0; i < 4; i++) {
            const float* xb = &bufA[gm[i] * 200];
            const float* hb = &bufB[gm[i] * 200];
            float r = sigf(xb[gk[i]] + hb[gk[i]]);
            float z = sigf(xb[64 + gk[i]] + hb[64 + gk[i]]);
            float n = tanhf_fast(xb[128 + gk[i]] + r * hb[128 + gk[i]]);
            float ho = h1s[gm[i] * 68 + gk[i]];
            h1s[gm[i] * 68 + gk[i]] = n + z * (ho - n);
        }
        __syncthreads();
    }

    // ---- epilogue: actions = relu(h1_last) @ fc3_w^T + fc3_b ----
    for (int idx = tid; idx < BM * At; idx += 128) {
        int mm = idx / At, a = idx - mm * At;
        float s = sfb[a];
        const float* wr = &sfw[a * 64];
        const float* hr = &h1s[mm * 68];
        #pragma unroll
        for (int k = 0; k < 64; k++) s += fmaxf(hr[k], 0.0f) * wr[k];
        out[(b0 + mm) * At + a] = s;
    }
}

// ---------------------------------------------------------------------------
// launch
// ---------------------------------------------------------------------------
extern "C" void kernel_launch(void* const* d_in, const int* in_sizes, int n_in,
                              void* d_out, int out_size) {
    const float* state = (const float*)d_in[0];
    const float* Wih0  = (const float*)d_in[1];
    const float* Whh0  = (const float*)d_in[2];
    const float* bih0  = (const float*)d_in[3];
    const float* bhh0  = (const float*)d_in[4];
    const float* Wih1  = (const float*)d_in[5];
    const float* Whh1  = (const float*)d_in[6];
    const float* bih1  = (const float*)d_in[7];
    const float* bhh1  = (const float*)d_in[8];
    const float* fc3w  = (const float*)d_in[9];
    const float* fc3b  = (const float*)d_in[10];
    float* out = (float*)d_out;

    const size_t sm1 = (size_t)(32 * 192 + 32 * 65) * sizeof(float4);
    const size_t sm2 = (size_t)(3 * 16 * 192) * sizeof(float4)
                     + (size_t)(1088 + 3200 + 576 + 1152 + 32) * sizeof(float);

    cudaFuncSetAttribute(gx0_kernel, cudaFuncAttributeMaxDynamicSharedMemorySize, (int)sm1);
    cudaFuncSetAttribute(gru_kernel, cudaFuncAttributeMaxDynamicSharedMemorySize, (int)sm2);

    gx0_kernel<<<(Bt * Tt) / 32, 256, sm1>>>(state, Wih0, bih0);
    gru_kernel<<<Bt / BM, 128, sm2>>>(Whh0, bhh0, Wih1, bih1, Whh1, bhh1, fc3w, fc3b, out);
}